// round 2
// baseline (speedup 1.0000x reference)
#include <cuda_runtime.h>

// TrajectoryGeneratorAR_goal: S=256 rollouts x N=64 agents, OBS=8 encoder LSTM
// steps, PRED=12 autoregressive decoder steps with pairwise pooling net.
// One CTA per rollout, 256 threads, everything resident in shared memory.
// Round 2: pooling inner loop converted to packed fma.rn.f32x2 (2 MAC / fma
// slot), j-tile reduced 4->2 and __launch_bounds__(256,2) so two CTAs
// co-reside per SM (single wave across the chip).

namespace {

constexpr int S_BATCH  = 256;
constexpr int NAG      = 64;
constexpr int BTOT     = S_BATCH * NAG;   // 16384
constexpr int OBS      = 8;
constexpr int PRED     = 12;
constexpr int H        = 16;
constexpr int NTHREADS = 256;

struct __align__(16) Smem {
    float h[NAG][17];          // padded stride 17
    float c[NAG][17];
    float ctx[NAG][17];
    float hjp[NAG][65];        // h_j @ W1h + b1, padded stride 65
    float curr[NAG][2];
    float outp[NAG][2];
    float goal[NAG][2];
    unsigned long long nmask[NAG];   // bit j: neighbor mask row i
    // weights
    alignas(16) float embW[32];
    alignas(16) float embB[16];
    alignas(16) float encWih[16*64];
    alignas(16) float encWhh[16*64];
    alignas(16) float encB[64];
    alignas(16) float decinW[18*16];
    alignas(16) float decinB[16];
    alignas(16) float decWih[16*64];
    alignas(16) float decWhh[16*64];
    alignas(16) float decB[64];
    alignas(16) float peW[32];
    alignas(16) float peB[16];
    alignas(16) float W1pT[64*16];   // transposed: [k][d]  (pool_W1 rows 0..15)
    alignas(16) float W1h [16*64];   // [d][k]             (pool_W1 rows 16..31)
    alignas(16) float b1  [64];
    alignas(16) float W2  [64*16];   // [k][u]
    alignas(16) float b2  [16];
    alignas(16) float h2p1W[18*16];
    alignas(16) float h2p1B[16];
    alignas(16) float h2p2W[16*4];
    alignas(16) float h2p2B[4];
};

__device__ __forceinline__ float sigm(float x)   { return 1.0f / (1.0f + __expf(-x)); }
__device__ __forceinline__ float tanh_f(float x) { return 2.0f / (1.0f + __expf(-2.0f * x)) - 1.0f; }

// ---- packed f32x2 helpers (Blackwell: fma.rn.f32x2, 2 MACs per fma slot) ----
__device__ __forceinline__ unsigned long long pk2(float lo, float hi) {
    unsigned long long r;
    asm("mov.b64 %0, {%1, %2};" : "=l"(r) : "f"(lo), "f"(hi));
    return r;
}
__device__ __forceinline__ void upk2(float& lo, float& hi, unsigned long long v) {
    asm("mov.b64 {%0, %1}, %2;" : "=f"(lo), "=f"(hi) : "l"(v));
}
__device__ __forceinline__ unsigned long long ffma2(unsigned long long a,
                                                    unsigned long long b,
                                                    unsigned long long c) {
    unsigned long long d;
    asm("fma.rn.f32x2 %0, %1, %2, %3;" : "=l"(d) : "l"(a), "l"(b), "l"(c));
    return d;
}

__device__ __forceinline__ void cpw(float* dst, const float* src, int n, int tid) {
    for (int k = tid; k < n; k += NTHREADS) dst[k] = src[k];
}

} // namespace

__global__ __launch_bounds__(NTHREADS, 2)
void traj_ar_kernel(
    const float* __restrict__ traj_rel,   // (OBS, BTOT, 2)
    const float* __restrict__ obs_pos,    // (OBS, BTOT, 2)
    const float* __restrict__ goal_g,     // (BTOT, 2)
    const float* __restrict__ embW, const float* __restrict__ embB,
    const float* __restrict__ encWih, const float* __restrict__ encWhh, const float* __restrict__ encB,
    const float* __restrict__ decinW, const float* __restrict__ decinB,
    const float* __restrict__ decWih, const float* __restrict__ decWhh, const float* __restrict__ decB,
    const float* __restrict__ peW, const float* __restrict__ peB,
    const float* __restrict__ W1, const float* __restrict__ b1,
    const float* __restrict__ W2, const float* __restrict__ b2,
    const float* __restrict__ h2p1W, const float* __restrict__ h2p1B,
    const float* __restrict__ h2p2W, const float* __restrict__ h2p2B,
    const int* __restrict__ nei,          // (BTOT, NAG)
    float* __restrict__ out, int out_size)
{
    extern __shared__ unsigned char smem_raw[];
    Smem& sm = *reinterpret_cast<Smem*>(smem_raw);
    const int tid = threadIdx.x;
    const int s   = blockIdx.x;

    // nll is exactly 0 (out = mu): zero the output tail beyond the preds.
    if (s == 0 && tid == 0) {
        for (int idx = PRED * BTOT * 2; idx < out_size; ++idx) out[idx] = 0.0f;
    }

    // ---------------- weight staging + state init ----------------
    cpw(sm.embW,  embW,  32,  tid);  cpw(sm.embB,  embB,  16, tid);
    cpw(sm.encWih, encWih, 1024, tid); cpw(sm.encWhh, encWhh, 1024, tid); cpw(sm.encB, encB, 64, tid);
    cpw(sm.decinW, decinW, 288, tid);  cpw(sm.decinB, decinB, 16, tid);
    cpw(sm.decWih, decWih, 1024, tid); cpw(sm.decWhh, decWhh, 1024, tid); cpw(sm.decB, decB, 64, tid);
    cpw(sm.peW, peW, 32, tid); cpw(sm.peB, peB, 16, tid);
    for (int idx = tid; idx < 1024; idx += NTHREADS) {   // W1pT[k][d] = W1[d][k]
        const int k = idx >> 4, d = idx & 15;
        sm.W1pT[idx] = W1[d * 64 + k];
    }
    cpw(sm.W1h, W1 + 1024, 1024, tid);
    cpw(sm.b1, b1, 64, tid); cpw(sm.W2, W2, 1024, tid); cpw(sm.b2, b2, 16, tid);
    cpw(sm.h2p1W, h2p1W, 288, tid); cpw(sm.h2p1B, h2p1B, 16, tid);
    cpw(sm.h2p2W, h2p2W, 64, tid);  cpw(sm.h2p2B, h2p2B, 4, tid);

    for (int idx = tid; idx < NAG * 17; idx += NTHREADS) {
        (&sm.h[0][0])[idx] = 0.0f; (&sm.c[0][0])[idx] = 0.0f; (&sm.ctx[0][0])[idx] = 0.0f;
    }
    if (tid < NAG) {
        sm.nmask[tid] = 0ull;
        const int b = s * NAG + tid;
        const float c0 = obs_pos[((OBS - 1) * BTOT + b) * 2 + 0];
        const float c1 = obs_pos[((OBS - 1) * BTOT + b) * 2 + 1];
        sm.curr[tid][0] = c0; sm.curr[tid][1] = c1;
        sm.outp[tid][0] = traj_rel[((OBS - 1) * BTOT + b) * 2 + 0];
        sm.outp[tid][1] = traj_rel[((OBS - 1) * BTOT + b) * 2 + 1];
        sm.goal[tid][0] = goal_g[b * 2 + 0] - c0;
        sm.goal[tid][1] = goal_g[b * 2 + 1] - c1;
    }
    __syncthreads();
    {   // neighbor mask -> 64-bit rows
        const int base = s * (NAG * NAG);
        #pragma unroll
        for (int r = 0; r < (NAG * NAG) / NTHREADS; ++r) {
            const int flat = r * NTHREADS + tid;
            if (nei[base + flat] != 0)
                atomicOr(&sm.nmask[flat >> 6], 1ull << (flat & 63));
        }
    }
    __syncthreads();

    const int a   = tid >> 2;   // agent owned by this quad
    const int sub = tid & 3;    // quad lane

    // ---------------- history encoder: LSTM over OBS steps ----------------
    for (int t = 0; t < OBS; ++t) {
        const int b = s * NAG + a;
        const float x0 = traj_rel[(t * BTOT + b) * 2 + 0];
        const float x1 = traj_rel[(t * BTOT + b) * 2 + 1];
        float emb[H];
        #pragma unroll
        for (int u = 0; u < H; ++u)
            emb[u] = fmaxf(fmaf(x0, sm.embW[u], fmaf(x1, sm.embW[16 + u], sm.embB[u])), 0.0f);
        float hold[H];
        #pragma unroll
        for (int d = 0; d < H; ++d) hold[d] = sm.h[a][d];
        float hn[4], cn[4];
        #pragma unroll
        for (int q = 0; q < 4; ++q) {
            const int u = sub * 4 + q;
            float gi = sm.encB[u], gf = sm.encB[16 + u], gg = sm.encB[32 + u], go = sm.encB[48 + u];
            #pragma unroll
            for (int d = 0; d < H; ++d) {
                const float e = emb[d], hd = hold[d];
                gi = fmaf(e, sm.encWih[d * 64 + u],        gi); gi = fmaf(hd, sm.encWhh[d * 64 + u],        gi);
                gf = fmaf(e, sm.encWih[d * 64 + 16 + u],   gf); gf = fmaf(hd, sm.encWhh[d * 64 + 16 + u],   gf);
                gg = fmaf(e, sm.encWih[d * 64 + 32 + u],   gg); gg = fmaf(hd, sm.encWhh[d * 64 + 32 + u],   gg);
                go = fmaf(e, sm.encWih[d * 64 + 48 + u],   go); go = fmaf(hd, sm.encWhh[d * 64 + 48 + u],   go);
            }
            const float cN = sigm(gf) * sm.c[a][u] + sigm(gi) * tanh_f(gg);
            cn[q] = cN; hn[q] = sigm(go) * tanh_f(cN);
        }
        __syncwarp();
        #pragma unroll
        for (int q = 0; q < 4; ++q) { sm.h[a][sub * 4 + q] = hn[q]; sm.c[a][sub * 4 + q] = cn[q]; }
        __syncwarp();
    }
    #pragma unroll
    for (int q = 0; q < 4; ++q) sm.c[a][sub * 4 + q] = 0.0f;
    __syncthreads();

    // ---------------- autoregressive decoder: PRED steps ----------------
    for (int step = 0; step < PRED; ++step) {
        // --- decoder input embed + LSTM gates (quad per agent) ---
        float ctxv[H];
        #pragma unroll
        for (int d = 0; d < H; ++d) ctxv[d] = sm.ctx[a][d];
        const float o0 = sm.outp[a][0], o1 = sm.outp[a][1];
        float emb[H];
        #pragma unroll
        for (int u = 0; u < H; ++u) {
            float acc = sm.decinB[u];
            #pragma unroll
            for (int d = 0; d < H; ++d) acc = fmaf(ctxv[d], sm.decinW[d * 16 + u], acc);
            acc = fmaf(o0, sm.decinW[256 + u], fmaf(o1, sm.decinW[272 + u], acc));
            emb[u] = fmaxf(acc, 0.0f);
        }
        float hold[H];
        #pragma unroll
        for (int d = 0; d < H; ++d) hold[d] = sm.h[a][d];
        float hn[4], cn[4];
        #pragma unroll
        for (int q = 0; q < 4; ++q) {
            const int u = sub * 4 + q;
            float gi = sm.decB[u], gf = sm.decB[16 + u], gg = sm.decB[32 + u], go = sm.decB[48 + u];
            #pragma unroll
            for (int d = 0; d < H; ++d) {
                const float e = emb[d], hd = hold[d];
                gi = fmaf(e, sm.decWih[d * 64 + u],        gi); gi = fmaf(hd, sm.decWhh[d * 64 + u],        gi);
                gf = fmaf(e, sm.decWih[d * 64 + 16 + u],   gf); gf = fmaf(hd, sm.decWhh[d * 64 + 16 + u],   gf);
                gg = fmaf(e, sm.decWih[d * 64 + 32 + u],   gg); gg = fmaf(hd, sm.decWhh[d * 64 + 32 + u],   gg);
                go = fmaf(e, sm.decWih[d * 64 + 48 + u],   go); go = fmaf(hd, sm.decWhh[d * 64 + 48 + u],   go);
            }
            const float cN = sigm(gf) * sm.c[a][u] + sigm(gi) * tanh_f(gg);
            cn[q] = cN; hn[q] = sigm(go) * tanh_f(cN);
        }
        __syncthreads();
        #pragma unroll
        for (int q = 0; q < 4; ++q) { sm.h[a][sub * 4 + q] = hn[q]; sm.c[a][sub * 4 + q] = cn[q]; }
        __syncthreads();

        // --- hjp[j][k] = h_j . W1h[:,k] + b1[k]  (i-independent half of layer 1) ---
        {
            const int j = a, k0 = sub * 16;
            float hv[H];
            #pragma unroll
            for (int d = 0; d < H; ++d) hv[d] = sm.h[j][d];
            #pragma unroll
            for (int kk = 0; kk < 16; ++kk) {
                const int k = k0 + kk;
                float acc = sm.b1[k];
                #pragma unroll
                for (int d = 0; d < H; ++d) acc = fmaf(hv[d], sm.W1h[d * 64 + k], acc);
                sm.hjp[j][k] = acc;
            }
        }
        __syncthreads();

        // --- pooling: i = a; this thread handles 16 j's in 8 tiles of 2,
        //     inner math in packed f32x2 (d-pairs for layer1, u-pairs for layer2) ---
        {
            const float cix = sm.curr[a][0], ciy = sm.curr[a][1];
            const unsigned long long mrow = sm.nmask[a];
            float ctxacc[H];
            #pragma unroll
            for (int u = 0; u < H; ++u) ctxacc[u] = 0.0f;

            #pragma unroll
            for (int tile = 0; tile < 8; ++tile) {
                const int j0 = sub * 16 + tile * 2;
                unsigned long long peP[2][8], mP[2][8];
                #pragma unroll
                for (int e = 0; e < 2; ++e) {
                    const int j = j0 + e;
                    const float dx = cix - sm.curr[j][0];
                    const float dy = ciy - sm.curr[j][1];
                    #pragma unroll
                    for (int d2 = 0; d2 < 8; ++d2) {
                        const float p0 = fmaxf(fmaf(dx, sm.peW[2*d2],   fmaf(dy, sm.peW[16 + 2*d2],   sm.peB[2*d2])),   0.0f);
                        const float p1 = fmaxf(fmaf(dx, sm.peW[2*d2+1], fmaf(dy, sm.peW[16 + 2*d2+1], sm.peB[2*d2+1])), 0.0f);
                        peP[e][d2] = pk2(p0, p1);
                        mP[e][d2]  = 0ull;
                    }
                }
                #pragma unroll 4
                for (int k = 0; k < 64; ++k) {
                    // w1 column k: 16 floats = 8 packed pairs, LDS.128 x4, warp-uniform
                    const ulonglong2* w1q = reinterpret_cast<const ulonglong2*>(sm.W1pT + (k << 4));
                    const ulonglong2 w1a = w1q[0], w1b = w1q[1], w1c = w1q[2], w1d = w1q[3];
                    // layer 1: acc = (hjp, 0) + sum_d pe*w1, packed over d-pairs
                    unsigned long long acc0 = pk2(sm.hjp[j0 + 0][k], 0.0f);
                    unsigned long long acc1 = pk2(sm.hjp[j0 + 1][k], 0.0f);
                    acc0 = ffma2(peP[0][0], w1a.x, acc0); acc1 = ffma2(peP[1][0], w1a.x, acc1);
                    acc0 = ffma2(peP[0][1], w1a.y, acc0); acc1 = ffma2(peP[1][1], w1a.y, acc1);
                    acc0 = ffma2(peP[0][2], w1b.x, acc0); acc1 = ffma2(peP[1][2], w1b.x, acc1);
                    acc0 = ffma2(peP[0][3], w1b.y, acc0); acc1 = ffma2(peP[1][3], w1b.y, acc1);
                    acc0 = ffma2(peP[0][4], w1c.x, acc0); acc1 = ffma2(peP[1][4], w1c.x, acc1);
                    acc0 = ffma2(peP[0][5], w1c.y, acc0); acc1 = ffma2(peP[1][5], w1c.y, acc1);
                    acc0 = ffma2(peP[0][6], w1d.x, acc0); acc1 = ffma2(peP[1][6], w1d.x, acc1);
                    acc0 = ffma2(peP[0][7], w1d.y, acc0); acc1 = ffma2(peP[1][7], w1d.y, acc1);
                    float l0, h0, l1, h1;
                    upk2(l0, h0, acc0); upk2(l1, h1, acc1);
                    const float av0 = fmaxf(l0 + h0, 0.0f);
                    const float av1 = fmaxf(l1 + h1, 0.0f);
                    const unsigned long long aP0 = pk2(av0, av0);
                    const unsigned long long aP1 = pk2(av1, av1);
                    // layer 2: m[u] += a * w2[k][u], packed over u-pairs
                    const ulonglong2* w2q = reinterpret_cast<const ulonglong2*>(sm.W2 + (k << 4));
                    const ulonglong2 w2a = w2q[0], w2b = w2q[1], w2c = w2q[2], w2d = w2q[3];
                    mP[0][0] = ffma2(aP0, w2a.x, mP[0][0]); mP[1][0] = ffma2(aP1, w2a.x, mP[1][0]);
                    mP[0][1] = ffma2(aP0, w2a.y, mP[0][1]); mP[1][1] = ffma2(aP1, w2a.y, mP[1][1]);
                    mP[0][2] = ffma2(aP0, w2b.x, mP[0][2]); mP[1][2] = ffma2(aP1, w2b.x, mP[1][2]);
                    mP[0][3] = ffma2(aP0, w2b.y, mP[0][3]); mP[1][3] = ffma2(aP1, w2b.y, mP[1][3]);
                    mP[0][4] = ffma2(aP0, w2c.x, mP[0][4]); mP[1][4] = ffma2(aP1, w2c.x, mP[1][4]);
                    mP[0][5] = ffma2(aP0, w2c.y, mP[0][5]); mP[1][5] = ffma2(aP1, w2c.y, mP[1][5]);
                    mP[0][6] = ffma2(aP0, w2d.x, mP[0][6]); mP[1][6] = ffma2(aP1, w2d.x, mP[1][6]);
                    mP[0][7] = ffma2(aP0, w2d.y, mP[0][7]); mP[1][7] = ffma2(aP1, w2d.y, mP[1][7]);
                }
                #pragma unroll
                for (int e = 0; e < 2; ++e) {
                    const float msk = ((mrow >> (j0 + e)) & 1ull) ? 1.0f : 0.0f;
                    #pragma unroll
                    for (int u2 = 0; u2 < 8; ++u2) {
                        float l, h;
                        upk2(l, h, mP[e][u2]);
                        ctxacc[2*u2]     = fmaf(msk, fmaxf(l + sm.b2[2*u2],     0.0f), ctxacc[2*u2]);
                        ctxacc[2*u2 + 1] = fmaf(msk, fmaxf(h + sm.b2[2*u2 + 1], 0.0f), ctxacc[2*u2 + 1]);
                    }
                }
            }
            // deterministic quad reduction (lanes sub=0..3 adjacent)
            #pragma unroll
            for (int u = 0; u < H; ++u) {
                float v = ctxacc[u];
                v += __shfl_down_sync(0xffffffffu, v, 2);
                v += __shfl_down_sync(0xffffffffu, v, 1);
                if (sub == 0) sm.ctx[a][u] = v;
            }
        }
        __syncthreads();

        // --- output head (one thread per agent) ---
        if (tid < NAG) {
            float hv[H], hh[H];
            #pragma unroll
            for (int u = 0; u < H; ++u) hv[u] = sm.h[tid][u] + sm.ctx[tid][u];
            const float g0 = sm.goal[tid][0], g1 = sm.goal[tid][1];
            #pragma unroll
            for (int u = 0; u < H; ++u) {
                float acc = sm.h2p1B[u];
                #pragma unroll
                for (int d = 0; d < H; ++d) acc = fmaf(hv[d], sm.h2p1W[d * 16 + u], acc);
                acc = fmaf(g0, sm.h2p1W[256 + u], fmaf(g1, sm.h2p1W[272 + u], acc));
                hh[u] = fmaxf(acc, 0.0f);
            }
            float mu0 = sm.h2p2B[0], mu1 = sm.h2p2B[1];
            #pragma unroll
            for (int d = 0; d < H; ++d) {
                mu0 = fmaf(hh[d], sm.h2p2W[d * 4 + 0], mu0);
                mu1 = fmaf(hh[d], sm.h2p2W[d * 4 + 1], mu1);
            }
            const int b = s * NAG + tid;
            out[(step * BTOT + b) * 2 + 0] = mu0;
            out[(step * BTOT + b) * 2 + 1] = mu1;
            sm.outp[tid][0] = mu0; sm.outp[tid][1] = mu1;
            sm.curr[tid][0] += mu0; sm.curr[tid][1] += mu1;
        }
        __syncthreads();
    }
}

extern "C" void kernel_launch(void* const* d_in, const int* in_sizes, int n_in,
                              void* d_out, int out_size)
{
    (void)in_sizes; (void)n_in;
    cudaFuncSetAttribute(traj_ar_kernel, cudaFuncAttributeMaxDynamicSharedMemorySize,
                         (int)sizeof(Smem));
    traj_ar_kernel<<<S_BATCH, NTHREADS, sizeof(Smem)>>>(
        (const float*)d_in[0],   // traj_rel
        (const float*)d_in[1],   // obs_traj_pos
        (const float*)d_in[2],   // sample_goal
        (const float*)d_in[4],  (const float*)d_in[5],    // enc_embed
        (const float*)d_in[6],  (const float*)d_in[7],  (const float*)d_in[8],   // enc_lstm
        (const float*)d_in[9],  (const float*)d_in[10],   // dec_in
        (const float*)d_in[11], (const float*)d_in[12], (const float*)d_in[13],  // dec_lstm
        (const float*)d_in[14], (const float*)d_in[15],   // pool_pe
        (const float*)d_in[16], (const float*)d_in[17],   // pool_W1, b1
        (const float*)d_in[18], (const float*)d_in[19],   // pool_W2, b2
        (const float*)d_in[20], (const float*)d_in[21],   // h2p1
        (const float*)d_in[22], (const float*)d_in[23],   // h2p2
        (const int*)d_in[24],    // nei_index
        (float*)d_out, out_size);
}

// round 3
// speedup vs baseline: 1.1442x; 1.1442x over previous
#include <cuda_runtime.h>

// TrajectoryGeneratorAR_goal: S=256 rollouts x N=64 agents, OBS=8 encoder LSTM
// steps, PRED=12 autoregressive decoder steps with pairwise pooling net.
// One CTA per rollout, 256 threads, everything resident in shared memory.
// Round 3: neighbor mask (~50% dense, static across steps) is compacted ONCE
// into a flat (i,j) pair list; each decoder step distributes the ~2048
// surviving pairs evenly across all 256 threads (perfect balance, ~2x less
// pooling work). Scalar FFMA only (the R2 f32x2 path regressed).

namespace {

constexpr int S_BATCH  = 256;
constexpr int NAG      = 64;
constexpr int BTOT     = S_BATCH * NAG;   // 16384
constexpr int OBS      = 8;
constexpr int PRED     = 12;
constexpr int H        = 16;
constexpr int NTHREADS = 256;
constexpr int MAXPAIRS = NAG * NAG;       // worst case mask all-ones

struct __align__(16) Smem {
    float h[NAG][17];          // padded stride 17
    float c[NAG][17];
    float ctx[NAG][17];
    float hjp[NAG][65];        // h_j @ W1h + b1, padded stride 65
    float curr[NAG][2];
    float outp[NAG][2];
    float goal[NAG][2];
    unsigned long long nmask[NAG];     // bit j: neighbor mask row i
    int   pfx[NAG + 1];                // prefix sum of per-i neighbor counts
    unsigned short plist[MAXPAIRS];    // compacted (i<<6)|j, sorted by i
    // weights
    alignas(16) float embW[32];
    alignas(16) float embB[16];
    alignas(16) float encWih[16*64];
    alignas(16) float encWhh[16*64];
    alignas(16) float encB[64];
    alignas(16) float decinW[18*16];
    alignas(16) float decinB[16];
    alignas(16) float decWih[16*64];
    alignas(16) float decWhh[16*64];
    alignas(16) float decB[64];
    alignas(16) float peW[32];
    alignas(16) float peB[16];
    alignas(16) float W1pT[64*16];   // transposed: [k][d]  (pool_W1 rows 0..15)
    alignas(16) float W1h [16*64];   // [d][k]             (pool_W1 rows 16..31)
    alignas(16) float b1  [64];
    alignas(16) float W2  [64*16];   // [k][u]
    alignas(16) float b2  [16];
    alignas(16) float h2p1W[18*16];
    alignas(16) float h2p1B[16];
    alignas(16) float h2p2W[16*4];
    alignas(16) float h2p2B[4];
};

__device__ __forceinline__ float sigm(float x)   { return 1.0f / (1.0f + __expf(-x)); }
__device__ __forceinline__ float tanh_f(float x) { return 2.0f / (1.0f + __expf(-2.0f * x)) - 1.0f; }

__device__ __forceinline__ void cpw(float* dst, const float* src, int n, int tid) {
    for (int k = tid; k < n; k += NTHREADS) dst[k] = src[k];
}

} // namespace

__global__ __launch_bounds__(NTHREADS)
void traj_ar_kernel(
    const float* __restrict__ traj_rel,   // (OBS, BTOT, 2)
    const float* __restrict__ obs_pos,    // (OBS, BTOT, 2)
    const float* __restrict__ goal_g,     // (BTOT, 2)
    const float* __restrict__ embW, const float* __restrict__ embB,
    const float* __restrict__ encWih, const float* __restrict__ encWhh, const float* __restrict__ encB,
    const float* __restrict__ decinW, const float* __restrict__ decinB,
    const float* __restrict__ decWih, const float* __restrict__ decWhh, const float* __restrict__ decB,
    const float* __restrict__ peW, const float* __restrict__ peB,
    const float* __restrict__ W1, const float* __restrict__ b1,
    const float* __restrict__ W2, const float* __restrict__ b2,
    const float* __restrict__ h2p1W, const float* __restrict__ h2p1B,
    const float* __restrict__ h2p2W, const float* __restrict__ h2p2B,
    const int* __restrict__ nei,          // (BTOT, NAG)
    float* __restrict__ out, int out_size)
{
    extern __shared__ unsigned char smem_raw[];
    Smem& sm = *reinterpret_cast<Smem*>(smem_raw);
    const int tid = threadIdx.x;
    const int s   = blockIdx.x;

    // nll is exactly 0 (out = mu): zero the output tail beyond the preds.
    if (s == 0 && tid == 0) {
        for (int idx = PRED * BTOT * 2; idx < out_size; ++idx) out[idx] = 0.0f;
    }

    // ---------------- weight staging + state init ----------------
    cpw(sm.embW,  embW,  32,  tid);  cpw(sm.embB,  embB,  16, tid);
    cpw(sm.encWih, encWih, 1024, tid); cpw(sm.encWhh, encWhh, 1024, tid); cpw(sm.encB, encB, 64, tid);
    cpw(sm.decinW, decinW, 288, tid);  cpw(sm.decinB, decinB, 16, tid);
    cpw(sm.decWih, decWih, 1024, tid); cpw(sm.decWhh, decWhh, 1024, tid); cpw(sm.decB, decB, 64, tid);
    cpw(sm.peW, peW, 32, tid); cpw(sm.peB, peB, 16, tid);
    for (int idx = tid; idx < 1024; idx += NTHREADS) {   // W1pT[k][d] = W1[d][k]
        const int k = idx >> 4, d = idx & 15;
        sm.W1pT[idx] = W1[d * 64 + k];
    }
    cpw(sm.W1h, W1 + 1024, 1024, tid);
    cpw(sm.b1, b1, 64, tid); cpw(sm.W2, W2, 1024, tid); cpw(sm.b2, b2, 16, tid);
    cpw(sm.h2p1W, h2p1W, 288, tid); cpw(sm.h2p1B, h2p1B, 16, tid);
    cpw(sm.h2p2W, h2p2W, 64, tid);  cpw(sm.h2p2B, h2p2B, 4, tid);

    for (int idx = tid; idx < NAG * 17; idx += NTHREADS) {
        (&sm.h[0][0])[idx] = 0.0f; (&sm.c[0][0])[idx] = 0.0f; (&sm.ctx[0][0])[idx] = 0.0f;
    }
    if (tid < NAG) {
        sm.nmask[tid] = 0ull;
        const int b = s * NAG + tid;
        const float c0 = obs_pos[((OBS - 1) * BTOT + b) * 2 + 0];
        const float c1 = obs_pos[((OBS - 1) * BTOT + b) * 2 + 1];
        sm.curr[tid][0] = c0; sm.curr[tid][1] = c1;
        sm.outp[tid][0] = traj_rel[((OBS - 1) * BTOT + b) * 2 + 0];
        sm.outp[tid][1] = traj_rel[((OBS - 1) * BTOT + b) * 2 + 1];
        sm.goal[tid][0] = goal_g[b * 2 + 0] - c0;
        sm.goal[tid][1] = goal_g[b * 2 + 1] - c1;
    }
    __syncthreads();
    {   // neighbor mask -> 64-bit rows
        const int base = s * (NAG * NAG);
        #pragma unroll
        for (int r = 0; r < (NAG * NAG) / NTHREADS; ++r) {
            const int flat = r * NTHREADS + tid;
            if (nei[base + flat] != 0)
                atomicOr(&sm.nmask[flat >> 6], 1ull << (flat & 63));
        }
    }
    __syncthreads();
    // ---- build compacted (i,j) pair list, sorted by i (mask is static) ----
    if (tid == 0) {
        int run = 0;
        #pragma unroll
        for (int i = 0; i < NAG; ++i) { sm.pfx[i] = run; run += __popcll(sm.nmask[i]); }
        sm.pfx[NAG] = run;
    }
    __syncthreads();
    if (tid < NAG) {
        unsigned long long m = sm.nmask[tid];
        int w = sm.pfx[tid];
        const unsigned short ibase = (unsigned short)(tid << 6);
        while (m) {
            const int j = __ffsll((long long)m) - 1;
            m &= m - 1;
            sm.plist[w++] = (unsigned short)(ibase | j);
        }
    }
    __syncthreads();
    const int P       = sm.pfx[NAG];
    const int pbase   = P >> 8;                 // P / NTHREADS
    const int prem    = P & (NTHREADS - 1);
    const int mystart = tid * pbase + (tid < prem ? tid : prem);
    const int mycnt   = pbase + (tid < prem ? 1 : 0);

    const int a   = tid >> 2;   // agent owned by this quad
    const int sub = tid & 3;    // quad lane

    // ---------------- history encoder: LSTM over OBS steps ----------------
    for (int t = 0; t < OBS; ++t) {
        const int b = s * NAG + a;
        const float x0 = traj_rel[(t * BTOT + b) * 2 + 0];
        const float x1 = traj_rel[(t * BTOT + b) * 2 + 1];
        float emb[H];
        #pragma unroll
        for (int u = 0; u < H; ++u)
            emb[u] = fmaxf(fmaf(x0, sm.embW[u], fmaf(x1, sm.embW[16 + u], sm.embB[u])), 0.0f);
        float hold[H];
        #pragma unroll
        for (int d = 0; d < H; ++d) hold[d] = sm.h[a][d];
        float hn[4], cn[4];
        #pragma unroll
        for (int q = 0; q < 4; ++q) {
            const int u = sub * 4 + q;
            float gi = sm.encB[u], gf = sm.encB[16 + u], gg = sm.encB[32 + u], go = sm.encB[48 + u];
            #pragma unroll
            for (int d = 0; d < H; ++d) {
                const float e = emb[d], hd = hold[d];
                gi = fmaf(e, sm.encWih[d * 64 + u],        gi); gi = fmaf(hd, sm.encWhh[d * 64 + u],        gi);
                gf = fmaf(e, sm.encWih[d * 64 + 16 + u],   gf); gf = fmaf(hd, sm.encWhh[d * 64 + 16 + u],   gf);
                gg = fmaf(e, sm.encWih[d * 64 + 32 + u],   gg); gg = fmaf(hd, sm.encWhh[d * 64 + 32 + u],   gg);
                go = fmaf(e, sm.encWih[d * 64 + 48 + u],   go); go = fmaf(hd, sm.encWhh[d * 64 + 48 + u],   go);
            }
            const float cN = sigm(gf) * sm.c[a][u] + sigm(gi) * tanh_f(gg);
            cn[q] = cN; hn[q] = sigm(go) * tanh_f(cN);
        }
        __syncwarp();
        #pragma unroll
        for (int q = 0; q < 4; ++q) { sm.h[a][sub * 4 + q] = hn[q]; sm.c[a][sub * 4 + q] = cn[q]; }
        __syncwarp();
    }
    #pragma unroll
    for (int q = 0; q < 4; ++q) sm.c[a][sub * 4 + q] = 0.0f;
    __syncthreads();

    // ---------------- autoregressive decoder: PRED steps ----------------
    for (int step = 0; step < PRED; ++step) {
        // --- decoder input embed + LSTM gates (quad per agent) ---
        float ctxv[H];
        #pragma unroll
        for (int d = 0; d < H; ++d) ctxv[d] = sm.ctx[a][d];
        const float o0 = sm.outp[a][0], o1 = sm.outp[a][1];
        float emb[H];
        #pragma unroll
        for (int u = 0; u < H; ++u) {
            float acc = sm.decinB[u];
            #pragma unroll
            for (int d = 0; d < H; ++d) acc = fmaf(ctxv[d], sm.decinW[d * 16 + u], acc);
            acc = fmaf(o0, sm.decinW[256 + u], fmaf(o1, sm.decinW[272 + u], acc));
            emb[u] = fmaxf(acc, 0.0f);
        }
        float hold[H];
        #pragma unroll
        for (int d = 0; d < H; ++d) hold[d] = sm.h[a][d];
        float hn[4], cn[4];
        #pragma unroll
        for (int q = 0; q < 4; ++q) {
            const int u = sub * 4 + q;
            float gi = sm.decB[u], gf = sm.decB[16 + u], gg = sm.decB[32 + u], go = sm.decB[48 + u];
            #pragma unroll
            for (int d = 0; d < H; ++d) {
                const float e = emb[d], hd = hold[d];
                gi = fmaf(e, sm.decWih[d * 64 + u],        gi); gi = fmaf(hd, sm.decWhh[d * 64 + u],        gi);
                gf = fmaf(e, sm.decWih[d * 64 + 16 + u],   gf); gf = fmaf(hd, sm.decWhh[d * 64 + 16 + u],   gf);
                gg = fmaf(e, sm.decWih[d * 64 + 32 + u],   gg); gg = fmaf(hd, sm.decWhh[d * 64 + 32 + u],   gg);
                go = fmaf(e, sm.decWih[d * 64 + 48 + u],   go); go = fmaf(hd, sm.decWhh[d * 64 + 48 + u],   go);
            }
            const float cN = sigm(gf) * sm.c[a][u] + sigm(gi) * tanh_f(gg);
            cn[q] = cN; hn[q] = sigm(go) * tanh_f(cN);
        }
        __syncthreads();
        #pragma unroll
        for (int q = 0; q < 4; ++q) { sm.h[a][sub * 4 + q] = hn[q]; sm.c[a][sub * 4 + q] = cn[q]; }
        __syncthreads();

        // --- hjp[j][k] = h_j . W1h[:,k] + b1[k]; also zero ctx for this step ---
        {
            const int j = a, k0 = sub * 16;
            float hv[H];
            #pragma unroll
            for (int d = 0; d < H; ++d) hv[d] = sm.h[j][d];
            #pragma unroll
            for (int kk = 0; kk < 16; ++kk) {
                const int k = k0 + kk;
                float acc = sm.b1[k];
                #pragma unroll
                for (int d = 0; d < H; ++d) acc = fmaf(hv[d], sm.W1h[d * 64 + k], acc);
                sm.hjp[j][k] = acc;
            }
        }
        for (int idx = tid; idx < NAG * 17; idx += NTHREADS) (&sm.ctx[0][0])[idx] = 0.0f;
        __syncthreads();

        // --- pooling over compacted pair list: mycnt pairs, balanced +-1 ---
        {
            int   cur_i = -1;
            float acc[H];
            for (int t = 0; t < mycnt; ++t) {
                const int pr = sm.plist[mystart + t];
                const int i = pr >> 6, j = pr & 63;
                const float dx = sm.curr[i][0] - sm.curr[j][0];
                const float dy = sm.curr[i][1] - sm.curr[j][1];
                float pe[H], m[H];
                #pragma unroll
                for (int u = 0; u < H; ++u) {
                    pe[u] = fmaxf(fmaf(dx, sm.peW[u], fmaf(dy, sm.peW[16 + u], sm.peB[u])), 0.0f);
                    m[u]  = 0.0f;
                }
                const float* __restrict__ hjrow = sm.hjp[j];
                #pragma unroll 4
                for (int k = 0; k < 64; ++k) {
                    const float4* w1q = reinterpret_cast<const float4*>(sm.W1pT + (k << 4));
                    const float4 wa = w1q[0], wb = w1q[1], wc = w1q[2], wd = w1q[3];
                    float av = hjrow[k];
                    av = fmaf(pe[0],  wa.x, av); av = fmaf(pe[1],  wa.y, av);
                    av = fmaf(pe[2],  wa.z, av); av = fmaf(pe[3],  wa.w, av);
                    av = fmaf(pe[4],  wb.x, av); av = fmaf(pe[5],  wb.y, av);
                    av = fmaf(pe[6],  wb.z, av); av = fmaf(pe[7],  wb.w, av);
                    av = fmaf(pe[8],  wc.x, av); av = fmaf(pe[9],  wc.y, av);
                    av = fmaf(pe[10], wc.z, av); av = fmaf(pe[11], wc.w, av);
                    av = fmaf(pe[12], wd.x, av); av = fmaf(pe[13], wd.y, av);
                    av = fmaf(pe[14], wd.z, av); av = fmaf(pe[15], wd.w, av);
                    av = fmaxf(av, 0.0f);
                    const float4* w2q = reinterpret_cast<const float4*>(sm.W2 + (k << 4));
                    const float4 va = w2q[0], vb = w2q[1], vc = w2q[2], vd = w2q[3];
                    m[0]  = fmaf(av, va.x, m[0]);  m[1]  = fmaf(av, va.y, m[1]);
                    m[2]  = fmaf(av, va.z, m[2]);  m[3]  = fmaf(av, va.w, m[3]);
                    m[4]  = fmaf(av, vb.x, m[4]);  m[5]  = fmaf(av, vb.y, m[5]);
                    m[6]  = fmaf(av, vb.z, m[6]);  m[7]  = fmaf(av, vb.w, m[7]);
                    m[8]  = fmaf(av, vc.x, m[8]);  m[9]  = fmaf(av, vc.y, m[9]);
                    m[10] = fmaf(av, vc.z, m[10]); m[11] = fmaf(av, vc.w, m[11]);
                    m[12] = fmaf(av, vd.x, m[12]); m[13] = fmaf(av, vd.y, m[13]);
                    m[14] = fmaf(av, vd.z, m[14]); m[15] = fmaf(av, vd.w, m[15]);
                }
                if (i == cur_i) {
                    #pragma unroll
                    for (int u = 0; u < H; ++u)
                        acc[u] += fmaxf(m[u] + sm.b2[u], 0.0f);
                } else {
                    if (cur_i >= 0) {
                        #pragma unroll
                        for (int u = 0; u < H; ++u) atomicAdd(&sm.ctx[cur_i][u], acc[u]);
                    }
                    cur_i = i;
                    #pragma unroll
                    for (int u = 0; u < H; ++u)
                        acc[u] = fmaxf(m[u] + sm.b2[u], 0.0f);
                }
            }
            if (cur_i >= 0) {
                #pragma unroll
                for (int u = 0; u < H; ++u) atomicAdd(&sm.ctx[cur_i][u], acc[u]);
            }
        }
        __syncthreads();

        // --- output head (one thread per agent) ---
        if (tid < NAG) {
            float hv[H], hh[H];
            #pragma unroll
            for (int u = 0; u < H; ++u) hv[u] = sm.h[tid][u] + sm.ctx[tid][u];
            const float g0 = sm.goal[tid][0], g1 = sm.goal[tid][1];
            #pragma unroll
            for (int u = 0; u < H; ++u) {
                float acc = sm.h2p1B[u];
                #pragma unroll
                for (int d = 0; d < H; ++d) acc = fmaf(hv[d], sm.h2p1W[d * 16 + u], acc);
                acc = fmaf(g0, sm.h2p1W[256 + u], fmaf(g1, sm.h2p1W[272 + u], acc));
                hh[u] = fmaxf(acc, 0.0f);
            }
            float mu0 = sm.h2p2B[0], mu1 = sm.h2p2B[1];
            #pragma unroll
            for (int d = 0; d < H; ++d) {
                mu0 = fmaf(hh[d], sm.h2p2W[d * 4 + 0], mu0);
                mu1 = fmaf(hh[d], sm.h2p2W[d * 4 + 1], mu1);
            }
            const int b = s * NAG + tid;
            out[(step * BTOT + b) * 2 + 0] = mu0;
            out[(step * BTOT + b) * 2 + 1] = mu1;
            sm.outp[tid][0] = mu0; sm.outp[tid][1] = mu1;
            sm.curr[tid][0] += mu0; sm.curr[tid][1] += mu1;
        }
        __syncthreads();
    }
}

extern "C" void kernel_launch(void* const* d_in, const int* in_sizes, int n_in,
                              void* d_out, int out_size)
{
    (void)in_sizes; (void)n_in;
    cudaFuncSetAttribute(traj_ar_kernel, cudaFuncAttributeMaxDynamicSharedMemorySize,
                         (int)sizeof(Smem));
    traj_ar_kernel<<<S_BATCH, NTHREADS, sizeof(Smem)>>>(
        (const float*)d_in[0],   // traj_rel
        (const float*)d_in[1],   // obs_traj_pos
        (const float*)d_in[2],   // sample_goal
        (const float*)d_in[4],  (const float*)d_in[5],    // enc_embed
        (const float*)d_in[6],  (const float*)d_in[7],  (const float*)d_in[8],   // enc_lstm
        (const float*)d_in[9],  (const float*)d_in[10],   // dec_in
        (const float*)d_in[11], (const float*)d_in[12], (const float*)d_in[13],  // dec_lstm
        (const float*)d_in[14], (const float*)d_in[15],   // pool_pe
        (const float*)d_in[16], (const float*)d_in[17],   // pool_W1, b1
        (const float*)d_in[18], (const float*)d_in[19],   // pool_W2, b2
        (const float*)d_in[20], (const float*)d_in[21],   // h2p1
        (const float*)d_in[22], (const float*)d_in[23],   // h2p2
        (const int*)d_in[24],    // nei_index
        (float*)d_out, out_size);
}

// round 4
// speedup vs baseline: 1.2398x; 1.0836x over previous
#include <cuda_runtime.h>

// TrajectoryGeneratorAR_goal: S=256 rollouts x N=64 agents, OBS=8 encoder LSTM
// steps, PRED=12 autoregressive decoder steps with pairwise pooling net.
// One CTA per rollout, 256 threads, everything resident in shared memory.
// Round 4: compacted neighbor pair list (R3) + restored ILP: 2 pairs per
// thread per k-loop, layer-1 dot split into two half-chains (4 independent
// FMA chains/thread), weight LDS amortized over the pair-tile.

namespace {

constexpr int S_BATCH  = 256;
constexpr int NAG      = 64;
constexpr int BTOT     = S_BATCH * NAG;   // 16384
constexpr int OBS      = 8;
constexpr int PRED     = 12;
constexpr int H        = 16;
constexpr int NTHREADS = 256;
constexpr int MAXPAIRS = NAG * NAG;

struct __align__(16) Smem {
    float h[NAG][17];
    float c[NAG][17];
    float ctx[NAG][17];
    float hjp[NAG][65];
    float curr[NAG][2];
    float outp[NAG][2];
    float goal[NAG][2];
    unsigned long long nmask[NAG];
    int   pfx[NAG + 1];
    unsigned short plist[MAXPAIRS];    // (i<<6)|j, sorted by i
    alignas(16) float embW[32];
    alignas(16) float embB[16];
    alignas(16) float encWih[16*64];
    alignas(16) float encWhh[16*64];
    alignas(16) float encB[64];
    alignas(16) float decinW[18*16];
    alignas(16) float decinB[16];
    alignas(16) float decWih[16*64];
    alignas(16) float decWhh[16*64];
    alignas(16) float decB[64];
    alignas(16) float peW[32];
    alignas(16) float peB[16];
    alignas(16) float W1pT[64*16];   // [k][d]  (pool_W1 rows 0..15, transposed)
    alignas(16) float W1h [16*64];   // [d][k]  (pool_W1 rows 16..31)
    alignas(16) float b1  [64];
    alignas(16) float W2  [64*16];   // [k][u]
    alignas(16) float b2  [16];
    alignas(16) float h2p1W[18*16];
    alignas(16) float h2p1B[16];
    alignas(16) float h2p2W[16*4];
    alignas(16) float h2p2B[4];
};

__device__ __forceinline__ float sigm(float x)   { return 1.0f / (1.0f + __expf(-x)); }
__device__ __forceinline__ float tanh_f(float x) { return 2.0f / (1.0f + __expf(-2.0f * x)) - 1.0f; }

__device__ __forceinline__ void cpw(float* dst, const float* src, int n, int tid) {
    for (int k = tid; k < n; k += NTHREADS) dst[k] = src[k];
}

} // namespace

__global__ __launch_bounds__(NTHREADS)
void traj_ar_kernel(
    const float* __restrict__ traj_rel,
    const float* __restrict__ obs_pos,
    const float* __restrict__ goal_g,
    const float* __restrict__ embW, const float* __restrict__ embB,
    const float* __restrict__ encWih, const float* __restrict__ encWhh, const float* __restrict__ encB,
    const float* __restrict__ decinW, const float* __restrict__ decinB,
    const float* __restrict__ decWih, const float* __restrict__ decWhh, const float* __restrict__ decB,
    const float* __restrict__ peW, const float* __restrict__ peB,
    const float* __restrict__ W1, const float* __restrict__ b1,
    const float* __restrict__ W2, const float* __restrict__ b2,
    const float* __restrict__ h2p1W, const float* __restrict__ h2p1B,
    const float* __restrict__ h2p2W, const float* __restrict__ h2p2B,
    const int* __restrict__ nei,
    float* __restrict__ out, int out_size)
{
    extern __shared__ unsigned char smem_raw[];
    Smem& sm = *reinterpret_cast<Smem*>(smem_raw);
    const int tid = threadIdx.x;
    const int s   = blockIdx.x;

    if (s == 0 && tid == 0) {
        for (int idx = PRED * BTOT * 2; idx < out_size; ++idx) out[idx] = 0.0f;
    }

    // ---------------- weight staging + state init ----------------
    cpw(sm.embW,  embW,  32,  tid);  cpw(sm.embB,  embB,  16, tid);
    cpw(sm.encWih, encWih, 1024, tid); cpw(sm.encWhh, encWhh, 1024, tid); cpw(sm.encB, encB, 64, tid);
    cpw(sm.decinW, decinW, 288, tid);  cpw(sm.decinB, decinB, 16, tid);
    cpw(sm.decWih, decWih, 1024, tid); cpw(sm.decWhh, decWhh, 1024, tid); cpw(sm.decB, decB, 64, tid);
    cpw(sm.peW, peW, 32, tid); cpw(sm.peB, peB, 16, tid);
    for (int idx = tid; idx < 1024; idx += NTHREADS) {
        const int k = idx >> 4, d = idx & 15;
        sm.W1pT[idx] = W1[d * 64 + k];
    }
    cpw(sm.W1h, W1 + 1024, 1024, tid);
    cpw(sm.b1, b1, 64, tid); cpw(sm.W2, W2, 1024, tid); cpw(sm.b2, b2, 16, tid);
    cpw(sm.h2p1W, h2p1W, 288, tid); cpw(sm.h2p1B, h2p1B, 16, tid);
    cpw(sm.h2p2W, h2p2W, 64, tid);  cpw(sm.h2p2B, h2p2B, 4, tid);

    for (int idx = tid; idx < NAG * 17; idx += NTHREADS) {
        (&sm.h[0][0])[idx] = 0.0f; (&sm.c[0][0])[idx] = 0.0f; (&sm.ctx[0][0])[idx] = 0.0f;
    }
    if (tid < NAG) {
        sm.nmask[tid] = 0ull;
        const int b = s * NAG + tid;
        const float c0 = obs_pos[((OBS - 1) * BTOT + b) * 2 + 0];
        const float c1 = obs_pos[((OBS - 1) * BTOT + b) * 2 + 1];
        sm.curr[tid][0] = c0; sm.curr[tid][1] = c1;
        sm.outp[tid][0] = traj_rel[((OBS - 1) * BTOT + b) * 2 + 0];
        sm.outp[tid][1] = traj_rel[((OBS - 1) * BTOT + b) * 2 + 1];
        sm.goal[tid][0] = goal_g[b * 2 + 0] - c0;
        sm.goal[tid][1] = goal_g[b * 2 + 1] - c1;
    }
    __syncthreads();
    {
        const int base = s * (NAG * NAG);
        #pragma unroll
        for (int r = 0; r < (NAG * NAG) / NTHREADS; ++r) {
            const int flat = r * NTHREADS + tid;
            if (nei[base + flat] != 0)
                atomicOr(&sm.nmask[flat >> 6], 1ull << (flat & 63));
        }
    }
    __syncthreads();
    // ---- compacted (i,j) pair list, sorted by i (mask static over steps) ----
    if (tid == 0) {
        int run = 0;
        #pragma unroll
        for (int i = 0; i < NAG; ++i) { sm.pfx[i] = run; run += __popcll(sm.nmask[i]); }
        sm.pfx[NAG] = run;
    }
    __syncthreads();
    if (tid < NAG) {
        unsigned long long m = sm.nmask[tid];
        int w = sm.pfx[tid];
        const unsigned short ibase = (unsigned short)(tid << 6);
        while (m) {
            const int j = __ffsll((long long)m) - 1;
            m &= m - 1;
            sm.plist[w++] = (unsigned short)(ibase | j);
        }
    }
    __syncthreads();
    const int P       = sm.pfx[NAG];
    const int pbase   = P >> 8;
    const int prem    = P & (NTHREADS - 1);
    const int mystart = tid * pbase + (tid < prem ? tid : prem);
    const int mycnt   = pbase + (tid < prem ? 1 : 0);

    const int a   = tid >> 2;
    const int sub = tid & 3;

    // ---------------- history encoder ----------------
    for (int t = 0; t < OBS; ++t) {
        const int b = s * NAG + a;
        const float x0 = traj_rel[(t * BTOT + b) * 2 + 0];
        const float x1 = traj_rel[(t * BTOT + b) * 2 + 1];
        float emb[H];
        #pragma unroll
        for (int u = 0; u < H; ++u)
            emb[u] = fmaxf(fmaf(x0, sm.embW[u], fmaf(x1, sm.embW[16 + u], sm.embB[u])), 0.0f);
        float hold[H];
        #pragma unroll
        for (int d = 0; d < H; ++d) hold[d] = sm.h[a][d];
        float hn[4], cn[4];
        #pragma unroll
        for (int q = 0; q < 4; ++q) {
            const int u = sub * 4 + q;
            float gi = sm.encB[u], gf = sm.encB[16 + u], gg = sm.encB[32 + u], go = sm.encB[48 + u];
            #pragma unroll
            for (int d = 0; d < H; ++d) {
                const float e = emb[d], hd = hold[d];
                gi = fmaf(e, sm.encWih[d * 64 + u],        gi); gi = fmaf(hd, sm.encWhh[d * 64 + u],        gi);
                gf = fmaf(e, sm.encWih[d * 64 + 16 + u],   gf); gf = fmaf(hd, sm.encWhh[d * 64 + 16 + u],   gf);
                gg = fmaf(e, sm.encWih[d * 64 + 32 + u],   gg); gg = fmaf(hd, sm.encWhh[d * 64 + 32 + u],   gg);
                go = fmaf(e, sm.encWih[d * 64 + 48 + u],   go); go = fmaf(hd, sm.encWhh[d * 64 + 48 + u],   go);
            }
            const float cN = sigm(gf) * sm.c[a][u] + sigm(gi) * tanh_f(gg);
            cn[q] = cN; hn[q] = sigm(go) * tanh_f(cN);
        }
        __syncwarp();
        #pragma unroll
        for (int q = 0; q < 4; ++q) { sm.h[a][sub * 4 + q] = hn[q]; sm.c[a][sub * 4 + q] = cn[q]; }
        __syncwarp();
    }
    #pragma unroll
    for (int q = 0; q < 4; ++q) sm.c[a][sub * 4 + q] = 0.0f;
    __syncthreads();

    // ---------------- autoregressive decoder ----------------
    for (int step = 0; step < PRED; ++step) {
        // decoder input embed + LSTM (quad per agent)
        float ctxv[H];
        #pragma unroll
        for (int d = 0; d < H; ++d) ctxv[d] = sm.ctx[a][d];
        const float o0 = sm.outp[a][0], o1 = sm.outp[a][1];
        float emb[H];
        #pragma unroll
        for (int u = 0; u < H; ++u) {
            float acc = sm.decinB[u];
            #pragma unroll
            for (int d = 0; d < H; ++d) acc = fmaf(ctxv[d], sm.decinW[d * 16 + u], acc);
            acc = fmaf(o0, sm.decinW[256 + u], fmaf(o1, sm.decinW[272 + u], acc));
            emb[u] = fmaxf(acc, 0.0f);
        }
        float hold[H];
        #pragma unroll
        for (int d = 0; d < H; ++d) hold[d] = sm.h[a][d];
        float hn[4], cn[4];
        #pragma unroll
        for (int q = 0; q < 4; ++q) {
            const int u = sub * 4 + q;
            float gi = sm.decB[u], gf = sm.decB[16 + u], gg = sm.decB[32 + u], go = sm.decB[48 + u];
            #pragma unroll
            for (int d = 0; d < H; ++d) {
                const float e = emb[d], hd = hold[d];
                gi = fmaf(e, sm.decWih[d * 64 + u],        gi); gi = fmaf(hd, sm.decWhh[d * 64 + u],        gi);
                gf = fmaf(e, sm.decWih[d * 64 + 16 + u],   gf); gf = fmaf(hd, sm.decWhh[d * 64 + 16 + u],   gf);
                gg = fmaf(e, sm.decWih[d * 64 + 32 + u],   gg); gg = fmaf(hd, sm.decWhh[d * 64 + 32 + u],   gg);
                go = fmaf(e, sm.decWih[d * 64 + 48 + u],   go); go = fmaf(hd, sm.decWhh[d * 64 + 48 + u],   go);
            }
            const float cN = sigm(gf) * sm.c[a][u] + sigm(gi) * tanh_f(gg);
            cn[q] = cN; hn[q] = sigm(go) * tanh_f(cN);
        }
        __syncthreads();
        #pragma unroll
        for (int q = 0; q < 4; ++q) { sm.h[a][sub * 4 + q] = hn[q]; sm.c[a][sub * 4 + q] = cn[q]; }
        __syncthreads();

        // hjp[j][k] = h_j . W1h[:,k] + b1[k]; zero ctx accumulators
        {
            const int j = a, k0 = sub * 16;
            float hv[H];
            #pragma unroll
            for (int d = 0; d < H; ++d) hv[d] = sm.h[j][d];
            #pragma unroll
            for (int kk = 0; kk < 16; ++kk) {
                const int k = k0 + kk;
                float acc = sm.b1[k];
                #pragma unroll
                for (int d = 0; d < H; ++d) acc = fmaf(hv[d], sm.W1h[d * 64 + k], acc);
                sm.hjp[j][k] = acc;
            }
        }
        for (int idx = tid; idx < NAG * 17; idx += NTHREADS) (&sm.ctx[0][0])[idx] = 0.0f;
        __syncthreads();

        // ---- pooling over pair list, 2 pairs per thread per k-loop ----
        {
            int   cur_i = -1;
            float acc[H];
            for (int t = 0; t < mycnt; t += 2) {
                const int  pr0  = sm.plist[mystart + t];
                const bool has1 = (t + 1 < mycnt);
                const int  pr1  = sm.plist[mystart + (has1 ? t + 1 : t)];
                const int i0 = pr0 >> 6, j0 = pr0 & 63;
                const int i1 = pr1 >> 6, j1 = pr1 & 63;
                const float dx0 = sm.curr[i0][0] - sm.curr[j0][0];
                const float dy0 = sm.curr[i0][1] - sm.curr[j0][1];
                const float dx1 = sm.curr[i1][0] - sm.curr[j1][0];
                const float dy1 = sm.curr[i1][1] - sm.curr[j1][1];
                float pe0[H], pe1[H], m0[H], m1[H];
                #pragma unroll
                for (int u = 0; u < H; ++u) {
                    pe0[u] = fmaxf(fmaf(dx0, sm.peW[u], fmaf(dy0, sm.peW[16 + u], sm.peB[u])), 0.0f);
                    pe1[u] = fmaxf(fmaf(dx1, sm.peW[u], fmaf(dy1, sm.peW[16 + u], sm.peB[u])), 0.0f);
                    m0[u] = 0.0f; m1[u] = 0.0f;
                }
                const float* __restrict__ hj0 = sm.hjp[j0];
                const float* __restrict__ hj1 = sm.hjp[j1];
                #pragma unroll 2
                for (int k = 0; k < 64; ++k) {
                    const float4* w1q = reinterpret_cast<const float4*>(sm.W1pT + (k << 4));
                    const float4 wa = w1q[0], wb = w1q[1], wc = w1q[2], wd = w1q[3];
                    // 4 independent half-chains (2 pairs x 2 halves)
                    float a0a = hj0[k], a0b = 0.0f;
                    float a1a = hj1[k], a1b = 0.0f;
                    a0a = fmaf(pe0[0],  wa.x, a0a); a0b = fmaf(pe0[8],  wc.x, a0b);
                    a1a = fmaf(pe1[0],  wa.x, a1a); a1b = fmaf(pe1[8],  wc.x, a1b);
                    a0a = fmaf(pe0[1],  wa.y, a0a); a0b = fmaf(pe0[9],  wc.y, a0b);
                    a1a = fmaf(pe1[1],  wa.y, a1a); a1b = fmaf(pe1[9],  wc.y, a1b);
                    a0a = fmaf(pe0[2],  wa.z, a0a); a0b = fmaf(pe0[10], wc.z, a0b);
                    a1a = fmaf(pe1[2],  wa.z, a1a); a1b = fmaf(pe1[10], wc.z, a1b);
                    a0a = fmaf(pe0[3],  wa.w, a0a); a0b = fmaf(pe0[11], wc.w, a0b);
                    a1a = fmaf(pe1[3],  wa.w, a1a); a1b = fmaf(pe1[11], wc.w, a1b);
                    a0a = fmaf(pe0[4],  wb.x, a0a); a0b = fmaf(pe0[12], wd.x, a0b);
                    a1a = fmaf(pe1[4],  wb.x, a1a); a1b = fmaf(pe1[12], wd.x, a1b);
                    a0a = fmaf(pe0[5],  wb.y, a0a); a0b = fmaf(pe0[13], wd.y, a0b);
                    a1a = fmaf(pe1[5],  wb.y, a1a); a1b = fmaf(pe1[13], wd.y, a1b);
                    a0a = fmaf(pe0[6],  wb.z, a0a); a0b = fmaf(pe0[14], wd.z, a0b);
                    a1a = fmaf(pe1[6],  wb.z, a1a); a1b = fmaf(pe1[14], wd.z, a1b);
                    a0a = fmaf(pe0[7],  wb.w, a0a); a0b = fmaf(pe0[15], wd.w, a0b);
                    a1a = fmaf(pe1[7],  wb.w, a1a); a1b = fmaf(pe1[15], wd.w, a1b);
                    const float av0 = fmaxf(a0a + a0b, 0.0f);
                    const float av1 = fmaxf(a1a + a1b, 0.0f);
                    const float4* w2q = reinterpret_cast<const float4*>(sm.W2 + (k << 4));
                    const float4 va = w2q[0], vb = w2q[1], vc = w2q[2], vd = w2q[3];
                    m0[0]  = fmaf(av0, va.x, m0[0]);  m1[0]  = fmaf(av1, va.x, m1[0]);
                    m0[1]  = fmaf(av0, va.y, m0[1]);  m1[1]  = fmaf(av1, va.y, m1[1]);
                    m0[2]  = fmaf(av0, va.z, m0[2]);  m1[2]  = fmaf(av1, va.z, m1[2]);
                    m0[3]  = fmaf(av0, va.w, m0[3]);  m1[3]  = fmaf(av1, va.w, m1[3]);
                    m0[4]  = fmaf(av0, vb.x, m0[4]);  m1[4]  = fmaf(av1, vb.x, m1[4]);
                    m0[5]  = fmaf(av0, vb.y, m0[5]);  m1[5]  = fmaf(av1, vb.y, m1[5]);
                    m0[6]  = fmaf(av0, vb.z, m0[6]);  m1[6]  = fmaf(av1, vb.z, m1[6]);
                    m0[7]  = fmaf(av0, vb.w, m0[7]);  m1[7]  = fmaf(av1, vb.w, m1[7]);
                    m0[8]  = fmaf(av0, vc.x, m0[8]);  m1[8]  = fmaf(av1, vc.x, m1[8]);
                    m0[9]  = fmaf(av0, vc.y, m0[9]);  m1[9]  = fmaf(av1, vc.y, m1[9]);
                    m0[10] = fmaf(av0, vc.z, m0[10]); m1[10] = fmaf(av1, vc.z, m1[10]);
                    m0[11] = fmaf(av0, vc.w, m0[11]); m1[11] = fmaf(av1, vc.w, m1[11]);
                    m0[12] = fmaf(av0, vd.x, m0[12]); m1[12] = fmaf(av1, vd.x, m1[12]);
                    m0[13] = fmaf(av0, vd.y, m0[13]); m1[13] = fmaf(av1, vd.y, m1[13]);
                    m0[14] = fmaf(av0, vd.z, m0[14]); m1[14] = fmaf(av1, vd.z, m1[14]);
                    m0[15] = fmaf(av0, vd.w, m0[15]); m1[15] = fmaf(av1, vd.w, m1[15]);
                }
                // epilogue pair 0
                if (i0 == cur_i) {
                    #pragma unroll
                    for (int u = 0; u < H; ++u) acc[u] += fmaxf(m0[u] + sm.b2[u], 0.0f);
                } else {
                    if (cur_i >= 0) {
                        #pragma unroll
                        for (int u = 0; u < H; ++u) atomicAdd(&sm.ctx[cur_i][u], acc[u]);
                    }
                    cur_i = i0;
                    #pragma unroll
                    for (int u = 0; u < H; ++u) acc[u] = fmaxf(m0[u] + sm.b2[u], 0.0f);
                }
                // epilogue pair 1
                if (has1) {
                    if (i1 == cur_i) {
                        #pragma unroll
                        for (int u = 0; u < H; ++u) acc[u] += fmaxf(m1[u] + sm.b2[u], 0.0f);
                    } else {
                        #pragma unroll
                        for (int u = 0; u < H; ++u) atomicAdd(&sm.ctx[cur_i][u], acc[u]);
                        cur_i = i1;
                        #pragma unroll
                        for (int u = 0; u < H; ++u) acc[u] = fmaxf(m1[u] + sm.b2[u], 0.0f);
                    }
                }
            }
            if (cur_i >= 0) {
                #pragma unroll
                for (int u = 0; u < H; ++u) atomicAdd(&sm.ctx[cur_i][u], acc[u]);
            }
        }
        __syncthreads();

        // output head (one thread per agent)
        if (tid < NAG) {
            float hv[H], hh[H];
            #pragma unroll
            for (int u = 0; u < H; ++u) hv[u] = sm.h[tid][u] + sm.ctx[tid][u];
            const float g0 = sm.goal[tid][0], g1 = sm.goal[tid][1];
            #pragma unroll
            for (int u = 0; u < H; ++u) {
                float acc = sm.h2p1B[u];
                #pragma unroll
                for (int d = 0; d < H; ++d) acc = fmaf(hv[d], sm.h2p1W[d * 16 + u], acc);
                acc = fmaf(g0, sm.h2p1W[256 + u], fmaf(g1, sm.h2p1W[272 + u], acc));
                hh[u] = fmaxf(acc, 0.0f);
            }
            float mu0 = sm.h2p2B[0], mu1 = sm.h2p2B[1];
            #pragma unroll
            for (int d = 0; d < H; ++d) {
                mu0 = fmaf(hh[d], sm.h2p2W[d * 4 + 0], mu0);
                mu1 = fmaf(hh[d], sm.h2p2W[d * 4 + 1], mu1);
            }
            const int b = s * NAG + tid;
            out[(step * BTOT + b) * 2 + 0] = mu0;
            out[(step * BTOT + b) * 2 + 1] = mu1;
            sm.outp[tid][0] = mu0; sm.outp[tid][1] = mu1;
            sm.curr[tid][0] += mu0; sm.curr[tid][1] += mu1;
        }
        __syncthreads();
    }
}

extern "C" void kernel_launch(void* const* d_in, const int* in_sizes, int n_in,
                              void* d_out, int out_size)
{
    (void)in_sizes; (void)n_in;
    cudaFuncSetAttribute(traj_ar_kernel, cudaFuncAttributeMaxDynamicSharedMemorySize,
                         (int)sizeof(Smem));
    traj_ar_kernel<<<S_BATCH, NTHREADS, sizeof(Smem)>>>(
        (const float*)d_in[0],
        (const float*)d_in[1],
        (const float*)d_in[2],
        (const float*)d_in[4],  (const float*)d_in[5],
        (const float*)d_in[6],  (const float*)d_in[7],  (const float*)d_in[8],
        (const float*)d_in[9],  (const float*)d_in[10],
        (const float*)d_in[11], (const float*)d_in[12], (const float*)d_in[13],
        (const float*)d_in[14], (const float*)d_in[15],
        (const float*)d_in[16], (const float*)d_in[17],
        (const float*)d_in[18], (const float*)d_in[19],
        (const float*)d_in[20], (const float*)d_in[21],
        (const float*)d_in[22], (const float*)d_in[23],
        (const int*)d_in[24],
        (float*)d_out, out_size);
}

// round 5
// speedup vs baseline: 1.2484x; 1.0070x over previous
#include <cuda_runtime.h>

// TrajectoryGeneratorAR_goal: S=256 rollouts x N=64 agents, OBS=8 encoder LSTM
// steps, PRED=12 autoregressive decoder steps with pairwise pooling net.
// One CTA per rollout, 256 threads, smem-resident.
// Round 5: occupancy 2 (launch_bounds(256,2) -> 16 warps/SM). Pooling goes
// back to j-tile=1 to fit 128 regs; latency hiding now comes from warps
// (4/SMSP) + 16 independent m[] accumulators, not giant per-thread tiles.

namespace {

constexpr int S_BATCH  = 256;
constexpr int NAG      = 64;
constexpr int BTOT     = S_BATCH * NAG;   // 16384
constexpr int OBS      = 8;
constexpr int PRED     = 12;
constexpr int H        = 16;
constexpr int NTHREADS = 256;
constexpr int MAXPAIRS = NAG * NAG;

struct __align__(16) Smem {
    float h[NAG][17];
    float c[NAG][17];
    float ctx[NAG][17];
    float hjp[NAG][65];
    float curr[NAG][2];
    float outp[NAG][2];
    float goal[NAG][2];
    unsigned long long nmask[NAG];
    int   pfx[NAG + 1];
    unsigned short plist[MAXPAIRS];    // (i<<6)|j, sorted by i
    alignas(16) float embW[32];
    alignas(16) float embB[16];
    alignas(16) float encWih[16*64];
    alignas(16) float encWhh[16*64];
    alignas(16) float encB[64];
    alignas(16) float decinW[18*16];
    alignas(16) float decinB[16];
    alignas(16) float decWih[16*64];
    alignas(16) float decWhh[16*64];
    alignas(16) float decB[64];
    alignas(16) float peW[32];
    alignas(16) float peB[16];
    alignas(16) float W1pT[64*16];   // [k][d]  (pool_W1 rows 0..15, transposed)
    alignas(16) float W1h [16*64];   // [d][k]  (pool_W1 rows 16..31)
    alignas(16) float b1  [64];
    alignas(16) float W2  [64*16];   // [k][u]
    alignas(16) float b2  [16];
    alignas(16) float h2p1W[18*16];
    alignas(16) float h2p1B[16];
    alignas(16) float h2p2W[16*4];
    alignas(16) float h2p2B[4];
};

__device__ __forceinline__ float sigm(float x)   { return 1.0f / (1.0f + __expf(-x)); }
__device__ __forceinline__ float tanh_f(float x) { return 2.0f / (1.0f + __expf(-2.0f * x)) - 1.0f; }

__device__ __forceinline__ void cpw(float* dst, const float* src, int n, int tid) {
    for (int k = tid; k < n; k += NTHREADS) dst[k] = src[k];
}

} // namespace

__global__ __launch_bounds__(NTHREADS, 2)
void traj_ar_kernel(
    const float* __restrict__ traj_rel,
    const float* __restrict__ obs_pos,
    const float* __restrict__ goal_g,
    const float* __restrict__ embW, const float* __restrict__ embB,
    const float* __restrict__ encWih, const float* __restrict__ encWhh, const float* __restrict__ encB,
    const float* __restrict__ decinW, const float* __restrict__ decinB,
    const float* __restrict__ decWih, const float* __restrict__ decWhh, const float* __restrict__ decB,
    const float* __restrict__ peW, const float* __restrict__ peB,
    const float* __restrict__ W1, const float* __restrict__ b1,
    const float* __restrict__ W2, const float* __restrict__ b2,
    const float* __restrict__ h2p1W, const float* __restrict__ h2p1B,
    const float* __restrict__ h2p2W, const float* __restrict__ h2p2B,
    const int* __restrict__ nei,
    float* __restrict__ out, int out_size)
{
    extern __shared__ unsigned char smem_raw[];
    Smem& sm = *reinterpret_cast<Smem*>(smem_raw);
    const int tid = threadIdx.x;
    const int s   = blockIdx.x;

    if (s == 0 && tid == 0) {
        for (int idx = PRED * BTOT * 2; idx < out_size; ++idx) out[idx] = 0.0f;
    }

    // ---------------- weight staging + state init ----------------
    cpw(sm.embW,  embW,  32,  tid);  cpw(sm.embB,  embB,  16, tid);
    cpw(sm.encWih, encWih, 1024, tid); cpw(sm.encWhh, encWhh, 1024, tid); cpw(sm.encB, encB, 64, tid);
    cpw(sm.decinW, decinW, 288, tid);  cpw(sm.decinB, decinB, 16, tid);
    cpw(sm.decWih, decWih, 1024, tid); cpw(sm.decWhh, decWhh, 1024, tid); cpw(sm.decB, decB, 64, tid);
    cpw(sm.peW, peW, 32, tid); cpw(sm.peB, peB, 16, tid);
    for (int idx = tid; idx < 1024; idx += NTHREADS) {
        const int k = idx >> 4, d = idx & 15;
        sm.W1pT[idx] = W1[d * 64 + k];
    }
    cpw(sm.W1h, W1 + 1024, 1024, tid);
    cpw(sm.b1, b1, 64, tid); cpw(sm.W2, W2, 1024, tid); cpw(sm.b2, b2, 16, tid);
    cpw(sm.h2p1W, h2p1W, 288, tid); cpw(sm.h2p1B, h2p1B, 16, tid);
    cpw(sm.h2p2W, h2p2W, 64, tid);  cpw(sm.h2p2B, h2p2B, 4, tid);

    for (int idx = tid; idx < NAG * 17; idx += NTHREADS) {
        (&sm.h[0][0])[idx] = 0.0f; (&sm.c[0][0])[idx] = 0.0f; (&sm.ctx[0][0])[idx] = 0.0f;
    }
    if (tid < NAG) {
        sm.nmask[tid] = 0ull;
        const int b = s * NAG + tid;
        const float c0 = obs_pos[((OBS - 1) * BTOT + b) * 2 + 0];
        const float c1 = obs_pos[((OBS - 1) * BTOT + b) * 2 + 1];
        sm.curr[tid][0] = c0; sm.curr[tid][1] = c1;
        sm.outp[tid][0] = traj_rel[((OBS - 1) * BTOT + b) * 2 + 0];
        sm.outp[tid][1] = traj_rel[((OBS - 1) * BTOT + b) * 2 + 1];
        sm.goal[tid][0] = goal_g[b * 2 + 0] - c0;
        sm.goal[tid][1] = goal_g[b * 2 + 1] - c1;
    }
    __syncthreads();
    {
        const int base = s * (NAG * NAG);
        #pragma unroll
        for (int r = 0; r < (NAG * NAG) / NTHREADS; ++r) {
            const int flat = r * NTHREADS + tid;
            if (nei[base + flat] != 0)
                atomicOr(&sm.nmask[flat >> 6], 1ull << (flat & 63));
        }
    }
    __syncthreads();
    // ---- compacted (i,j) pair list, sorted by i (mask static over steps) ----
    if (tid == 0) {
        int run = 0;
        #pragma unroll
        for (int i = 0; i < NAG; ++i) { sm.pfx[i] = run; run += __popcll(sm.nmask[i]); }
        sm.pfx[NAG] = run;
    }
    __syncthreads();
    if (tid < NAG) {
        unsigned long long m = sm.nmask[tid];
        int w = sm.pfx[tid];
        const unsigned short ibase = (unsigned short)(tid << 6);
        while (m) {
            const int j = __ffsll((long long)m) - 1;
            m &= m - 1;
            sm.plist[w++] = (unsigned short)(ibase | j);
        }
    }
    __syncthreads();
    const int P       = sm.pfx[NAG];
    const int pbase   = P >> 8;
    const int prem    = P & (NTHREADS - 1);
    const int mystart = tid * pbase + (tid < prem ? tid : prem);
    const int mycnt   = pbase + (tid < prem ? 1 : 0);

    const int a   = tid >> 2;
    const int sub = tid & 3;

    // ---------------- history encoder ----------------
    for (int t = 0; t < OBS; ++t) {
        const int b = s * NAG + a;
        const float x0 = traj_rel[(t * BTOT + b) * 2 + 0];
        const float x1 = traj_rel[(t * BTOT + b) * 2 + 1];
        float emb[H];
        #pragma unroll
        for (int u = 0; u < H; ++u)
            emb[u] = fmaxf(fmaf(x0, sm.embW[u], fmaf(x1, sm.embW[16 + u], sm.embB[u])), 0.0f);
        float hold[H];
        #pragma unroll
        for (int d = 0; d < H; ++d) hold[d] = sm.h[a][d];
        float hn[4], cn[4];
        #pragma unroll
        for (int q = 0; q < 4; ++q) {
            const int u = sub * 4 + q;
            float gi = sm.encB[u], gf = sm.encB[16 + u], gg = sm.encB[32 + u], go = sm.encB[48 + u];
            #pragma unroll
            for (int d = 0; d < H; ++d) {
                const float e = emb[d], hd = hold[d];
                gi = fmaf(e, sm.encWih[d * 64 + u],        gi); gi = fmaf(hd, sm.encWhh[d * 64 + u],        gi);
                gf = fmaf(e, sm.encWih[d * 64 + 16 + u],   gf); gf = fmaf(hd, sm.encWhh[d * 64 + 16 + u],   gf);
                gg = fmaf(e, sm.encWih[d * 64 + 32 + u],   gg); gg = fmaf(hd, sm.encWhh[d * 64 + 32 + u],   gg);
                go = fmaf(e, sm.encWih[d * 64 + 48 + u],   go); go = fmaf(hd, sm.encWhh[d * 64 + 48 + u],   go);
            }
            const float cN = sigm(gf) * sm.c[a][u] + sigm(gi) * tanh_f(gg);
            cn[q] = cN; hn[q] = sigm(go) * tanh_f(cN);
        }
        __syncwarp();
        #pragma unroll
        for (int q = 0; q < 4; ++q) { sm.h[a][sub * 4 + q] = hn[q]; sm.c[a][sub * 4 + q] = cn[q]; }
        __syncwarp();
    }
    #pragma unroll
    for (int q = 0; q < 4; ++q) sm.c[a][sub * 4 + q] = 0.0f;
    __syncthreads();

    // ---------------- autoregressive decoder ----------------
    for (int step = 0; step < PRED; ++step) {
        // decoder input embed + LSTM (quad per agent)
        float ctxv[H];
        #pragma unroll
        for (int d = 0; d < H; ++d) ctxv[d] = sm.ctx[a][d];
        const float o0 = sm.outp[a][0], o1 = sm.outp[a][1];
        float emb[H];
        #pragma unroll
        for (int u = 0; u < H; ++u) {
            float acc = sm.decinB[u];
            #pragma unroll
            for (int d = 0; d < H; ++d) acc = fmaf(ctxv[d], sm.decinW[d * 16 + u], acc);
            acc = fmaf(o0, sm.decinW[256 + u], fmaf(o1, sm.decinW[272 + u], acc));
            emb[u] = fmaxf(acc, 0.0f);
        }
        float hold[H];
        #pragma unroll
        for (int d = 0; d < H; ++d) hold[d] = sm.h[a][d];
        float hn[4], cn[4];
        #pragma unroll
        for (int q = 0; q < 4; ++q) {
            const int u = sub * 4 + q;
            float gi = sm.decB[u], gf = sm.decB[16 + u], gg = sm.decB[32 + u], go = sm.decB[48 + u];
            #pragma unroll
            for (int d = 0; d < H; ++d) {
                const float e = emb[d], hd = hold[d];
                gi = fmaf(e, sm.decWih[d * 64 + u],        gi); gi = fmaf(hd, sm.decWhh[d * 64 + u],        gi);
                gf = fmaf(e, sm.decWih[d * 64 + 16 + u],   gf); gf = fmaf(hd, sm.decWhh[d * 64 + 16 + u],   gf);
                gg = fmaf(e, sm.decWih[d * 64 + 32 + u],   gg); gg = fmaf(hd, sm.decWhh[d * 64 + 32 + u],   gg);
                go = fmaf(e, sm.decWih[d * 64 + 48 + u],   go); go = fmaf(hd, sm.decWhh[d * 64 + 48 + u],   go);
            }
            const float cN = sigm(gf) * sm.c[a][u] + sigm(gi) * tanh_f(gg);
            cn[q] = cN; hn[q] = sigm(go) * tanh_f(cN);
        }
        __syncthreads();
        #pragma unroll
        for (int q = 0; q < 4; ++q) { sm.h[a][sub * 4 + q] = hn[q]; sm.c[a][sub * 4 + q] = cn[q]; }
        __syncthreads();

        // hjp[j][k] = h_j . W1h[:,k] + b1[k]; zero ctx accumulators
        {
            const int j = a, k0 = sub * 16;
            float hv[H];
            #pragma unroll
            for (int d = 0; d < H; ++d) hv[d] = sm.h[j][d];
            #pragma unroll
            for (int kk = 0; kk < 16; ++kk) {
                const int k = k0 + kk;
                float acc = sm.b1[k];
                #pragma unroll
                for (int d = 0; d < H; ++d) acc = fmaf(hv[d], sm.W1h[d * 64 + k], acc);
                sm.hjp[j][k] = acc;
            }
        }
        for (int idx = tid; idx < NAG * 17; idx += NTHREADS) (&sm.ctx[0][0])[idx] = 0.0f;
        __syncthreads();

        // ---- pooling over pair list: 1 pair per k-loop, occ-2 friendly ----
        {
            int   cur_i = -1;
            float acc[H];
            for (int t = 0; t < mycnt; ++t) {
                const int pr = sm.plist[mystart + t];
                const int i = pr >> 6, j = pr & 63;
                const float dx = sm.curr[i][0] - sm.curr[j][0];
                const float dy = sm.curr[i][1] - sm.curr[j][1];
                float pe[H], m[H];
                #pragma unroll
                for (int u = 0; u < H; ++u) {
                    pe[u] = fmaxf(fmaf(dx, sm.peW[u], fmaf(dy, sm.peW[16 + u], sm.peB[u])), 0.0f);
                    m[u]  = 0.0f;
                }
                const float* __restrict__ hjrow = sm.hjp[j];
                #pragma unroll 2
                for (int k = 0; k < 64; ++k) {
                    const float4* w1q = reinterpret_cast<const float4*>(sm.W1pT + (k << 4));
                    const float4 wa = w1q[0], wb = w1q[1], wc = w1q[2], wd = w1q[3];
                    // two independent half-chains
                    float aA = hjrow[k], aB = 0.0f;
                    aA = fmaf(pe[0],  wa.x, aA); aB = fmaf(pe[8],  wc.x, aB);
                    aA = fmaf(pe[1],  wa.y, aA); aB = fmaf(pe[9],  wc.y, aB);
                    aA = fmaf(pe[2],  wa.z, aA); aB = fmaf(pe[10], wc.z, aB);
                    aA = fmaf(pe[3],  wa.w, aA); aB = fmaf(pe[11], wc.w, aB);
                    aA = fmaf(pe[4],  wb.x, aA); aB = fmaf(pe[12], wd.x, aB);
                    aA = fmaf(pe[5],  wb.y, aA); aB = fmaf(pe[13], wd.y, aB);
                    aA = fmaf(pe[6],  wb.z, aA); aB = fmaf(pe[14], wd.z, aB);
                    aA = fmaf(pe[7],  wb.w, aA); aB = fmaf(pe[15], wd.w, aB);
                    const float av = fmaxf(aA + aB, 0.0f);
                    const float4* w2q = reinterpret_cast<const float4*>(sm.W2 + (k << 4));
                    const float4 va = w2q[0], vb = w2q[1], vc = w2q[2], vd = w2q[3];
                    m[0]  = fmaf(av, va.x, m[0]);  m[1]  = fmaf(av, va.y, m[1]);
                    m[2]  = fmaf(av, va.z, m[2]);  m[3]  = fmaf(av, va.w, m[3]);
                    m[4]  = fmaf(av, vb.x, m[4]);  m[5]  = fmaf(av, vb.y, m[5]);
                    m[6]  = fmaf(av, vb.z, m[6]);  m[7]  = fmaf(av, vb.w, m[7]);
                    m[8]  = fmaf(av, vc.x, m[8]);  m[9]  = fmaf(av, vc.y, m[9]);
                    m[10] = fmaf(av, vc.z, m[10]); m[11] = fmaf(av, vc.w, m[11]);
                    m[12] = fmaf(av, vd.x, m[12]); m[13] = fmaf(av, vd.y, m[13]);
                    m[14] = fmaf(av, vd.z, m[14]); m[15] = fmaf(av, vd.w, m[15]);
                }
                if (i == cur_i) {
                    #pragma unroll
                    for (int u = 0; u < H; ++u) acc[u] += fmaxf(m[u] + sm.b2[u], 0.0f);
                } else {
                    if (cur_i >= 0) {
                        #pragma unroll
                        for (int u = 0; u < H; ++u) atomicAdd(&sm.ctx[cur_i][u], acc[u]);
                    }
                    cur_i = i;
                    #pragma unroll
                    for (int u = 0; u < H; ++u) acc[u] = fmaxf(m[u] + sm.b2[u], 0.0f);
                }
            }
            if (cur_i >= 0) {
                #pragma unroll
                for (int u = 0; u < H; ++u) atomicAdd(&sm.ctx[cur_i][u], acc[u]);
            }
        }
        __syncthreads();

        // output head (one thread per agent)
        if (tid < NAG) {
            float hv[H], hh[H];
            #pragma unroll
            for (int u = 0; u < H; ++u) hv[u] = sm.h[tid][u] + sm.ctx[tid][u];
            const float g0 = sm.goal[tid][0], g1 = sm.goal[tid][1];
            #pragma unroll
            for (int u = 0; u < H; ++u) {
                float acc = sm.h2p1B[u];
                #pragma unroll
                for (int d = 0; d < H; ++d) acc = fmaf(hv[d], sm.h2p1W[d * 16 + u], acc);
                acc = fmaf(g0, sm.h2p1W[256 + u], fmaf(g1, sm.h2p1W[272 + u], acc));
                hh[u] = fmaxf(acc, 0.0f);
            }
            float mu0 = sm.h2p2B[0], mu1 = sm.h2p2B[1];
            #pragma unroll
            for (int d = 0; d < H; ++d) {
                mu0 = fmaf(hh[d], sm.h2p2W[d * 4 + 0], mu0);
                mu1 = fmaf(hh[d], sm.h2p2W[d * 4 + 1], mu1);
            }
            const int b = s * NAG + tid;
            out[(step * BTOT + b) * 2 + 0] = mu0;
            out[(step * BTOT + b) * 2 + 1] = mu1;
            sm.outp[tid][0] = mu0; sm.outp[tid][1] = mu1;
            sm.curr[tid][0] += mu0; sm.curr[tid][1] += mu1;
        }
        __syncthreads();
    }
}

extern "C" void kernel_launch(void* const* d_in, const int* in_sizes, int n_in,
                              void* d_out, int out_size)
{
    (void)in_sizes; (void)n_in;
    cudaFuncSetAttribute(traj_ar_kernel, cudaFuncAttributeMaxDynamicSharedMemorySize,
                         (int)sizeof(Smem));
    traj_ar_kernel<<<S_BATCH, NTHREADS, sizeof(Smem)>>>(
        (const float*)d_in[0],
        (const float*)d_in[1],
        (const float*)d_in[2],
        (const float*)d_in[4],  (const float*)d_in[5],
        (const float*)d_in[6],  (const float*)d_in[7],  (const float*)d_in[8],
        (const float*)d_in[9],  (const float*)d_in[10],
        (const float*)d_in[11], (const float*)d_in[12], (const float*)d_in[13],
        (const float*)d_in[14], (const float*)d_in[15],
        (const float*)d_in[16], (const float*)d_in[17],
        (const float*)d_in[18], (const float*)d_in[19],
        (const float*)d_in[20], (const float*)d_in[21],
        (const float*)d_in[22], (const float*)d_in[23],
        (const int*)d_in[24],
        (float*)d_out, out_size);
}